// round 14
// baseline (speedup 1.0000x reference)
#include <cuda_runtime.h>
#include <cuda.h>
#include <cuda_fp16.h>
#include <math.h>
#include <stdint.h>

// ---------------- problem constants ----------------
#define NTOK   (32*1024)        // B*N rows per input
#define NROWS  (2*NTOK)
#define DIM    768
#define HID    192
#define NC     1920             // fused output cols: Z|V|Pa|Pb
#define NKT    12               // 12 k-tiles of 64 halves

// GEMM tiling: 128x128 CTA tile, 8 warps (4m x 2n), warp tile 32x64, k-tile 64
#define BM 128
#define BN 128
#define TILE_BYTES 16384                  // 128 rows x 128B (64 halves)
#define STAGE_BYTES (2*TILE_BYTES)
#define NSTAGE 3
#define SMEM_TOTAL (1024 + NSTAGE*STAGE_BYTES + 64)
// epilogue staging: 128 rows x 272B (136 halves, padded) = 34816 B, reuses stages
#define EPI_ROW_B 272

// ---------------- scratch ----------------
__device__ __align__(1024) __half g_Wcath[(size_t)NC*DIM];     // fp16 [1920,768]: Gh|WvT|W1aT|W1bT
__device__ __align__(1024) __half g_Wkqh[(size_t)2*DIM*DIM];   // fp16 [Wk;Wq]
__device__ __align__(1024) __half g_Xh[(size_t)NROWS*DIM];     // fp16 [x1;x2]
__device__ __align__(1024) __half g_Ch[(size_t)NROWS*NC];      // fp16 [C1;C2]

// ---------------- device helpers ----------------
__device__ __forceinline__ uint32_t smem_u32(const void* p) {
    uint32_t a;
    asm("{ .reg .u64 t; cvta.to.shared.u64 t, %1; cvt.u32.u64 %0, t; }" : "=r"(a) : "l"(p));
    return a;
}
__device__ __forceinline__ uint32_t sw128(uint32_t off) { return off ^ ((off >> 3) & 0x70); }

#define MBAR_INIT(a, c) asm volatile("mbarrier.init.shared.b64 [%0], %1;" :: "r"(a), "r"(c) : "memory")
#define MBAR_EXPECT(a, bytes) \
    asm volatile("mbarrier.arrive.expect_tx.shared.b64 _, [%0], %1;" :: "r"(a), "r"(bytes) : "memory")
#define MBAR_WAIT(a, ph) do { \
    uint32_t _m = (a), _p = (ph), _d; \
    asm volatile("{ .reg .pred p; mbarrier.try_wait.parity.acquire.cta.shared::cta.b64 p, [%1], %2; selp.b32 %0,1,0,p; }" \
        : "=r"(_d) : "r"(_m), "r"(_p) : "memory"); \
    if (!_d) { \
        asm volatile("{ .reg .pred P1; WL_%=: mbarrier.try_wait.parity.acquire.cta.shared::cta.b64 P1, [%0], %1, 0x989680;" \
                     " @P1 bra.uni WD_%=; bra.uni WL_%=; WD_%=: }" :: "r"(_m), "r"(_p) : "memory"); \
    } } while(0)

__device__ __forceinline__ void tma_2d(uint32_t dst, const void* tmap, int x, int y, uint32_t mbar) {
    asm volatile("cp.async.bulk.tensor.2d.shared::cta.global.tile.mbarrier::complete_tx::bytes "
                 "[%0], [%1, {%2, %3}], [%4];"
                 :: "r"(dst), "l"(tmap), "r"(x), "r"(y), "r"(mbar) : "memory");
}
__device__ __forceinline__ void ldsm_x4(uint32_t* r, uint32_t addr) {
    asm volatile("ldmatrix.sync.aligned.m8n8.x4.shared.b16 {%0,%1,%2,%3}, [%4];"
                 : "=r"(r[0]), "=r"(r[1]), "=r"(r[2]), "=r"(r[3]) : "r"(addr));
}
__device__ __forceinline__ void mma_f16(float* c, const uint32_t* a, const uint32_t* b) {
    asm volatile("mma.sync.aligned.m16n8k16.row.col.f32.f16.f16.f32 "
                 "{%0,%1,%2,%3}, {%4,%5,%6,%7}, {%8,%9}, {%0,%1,%2,%3};"
                 : "+f"(c[0]), "+f"(c[1]), "+f"(c[2]), "+f"(c[3])
                 : "r"(a[0]), "r"(a[1]), "r"(a[2]), "r"(a[3]), "r"(b[0]), "r"(b[1]));
}

// ---------------- fp16 TMA GEMM: Ch[·,ldC] = A[·,768] @ Bt[·,768]^T -----------
// fp16 output via smem-staged, fully-coalesced uint4 stores.
__global__ void __launch_bounds__(256, 2)
gemm_f16_kernel(const __grid_constant__ CUtensorMap tmap_a,
                const __grid_constant__ CUtensorMap tmap_b,
                __half* __restrict__ Ch, int ldC) {
    extern __shared__ char smem[];
    const uint32_t sraw = smem_u32(smem);
    const uint32_t tbase = (sraw + 1023u) & ~1023u;
    char* tptr = smem + (tbase - sraw);
    const uint32_t mbar0 = tbase + NSTAGE * STAGE_BYTES;

    const int tid = threadIdx.x;
    const int lane = tid & 31, wid = tid >> 5;
    const int l4 = lane >> 2, lk = lane & 3;
    const int row0 = blockIdx.y * BM;
    const int col0 = blockIdx.x * BN;
    const int m0 = (wid & 3) * 32;
    const int n0 = (wid >> 2) * 64;

    const int lrow = (lane & 7) + 8 * ((lane >> 3) & 1);
    const uint32_t kseg = ((uint32_t)(lane >> 4)) << 4;   // 0 or 16 bytes

    if (tid == 0) {
        #pragma unroll
        for (int s = 0; s < NSTAGE; s++) MBAR_INIT(mbar0 + 8 * s, 1);
    }
    __syncthreads();

    if (tid == 0) {
        #pragma unroll
        for (int t = 0; t < 2; t++) {
            const uint32_t mb = mbar0 + 8 * t;
            const uint32_t sa = tbase + t * STAGE_BYTES;
            MBAR_EXPECT(mb, STAGE_BYTES);
            tma_2d(sa,              &tmap_a, t * 64, row0, mb);
            tma_2d(sa + TILE_BYTES, &tmap_b, t * 64, col0, mb);
        }
    }

    float acc[2][8][4];
    #pragma unroll
    for (int mt = 0; mt < 2; mt++)
        #pragma unroll
        for (int nt = 0; nt < 8; nt++)
            #pragma unroll
            for (int j = 0; j < 4; j++) acc[mt][nt][j] = 0.f;

    for (int kt = 0; kt < NKT; kt++) {
        const int s = kt % 3;
        __syncthreads();   // readers of stage (kt+2)%3 finished at kt-1
        if (tid == 0 && kt + 2 < NKT) {
            const int t = kt + 2, s2 = t % 3;
            const uint32_t mb = mbar0 + 8 * s2;
            const uint32_t sa = tbase + s2 * STAGE_BYTES;
            MBAR_EXPECT(mb, STAGE_BYTES);
            tma_2d(sa,              &tmap_a, t * 64, row0, mb);
            tma_2d(sa + TILE_BYTES, &tmap_b, t * 64, col0, mb);
        }
        MBAR_WAIT(mbar0 + 8 * s, (kt / 3) & 1);

        const uint32_t sa = tbase + s * STAGE_BYTES;
        const uint32_t sb = sa + TILE_BYTES;

        #pragma unroll
        for (int ks = 0; ks < 4; ks++) {
            const uint32_t kbyte = ks * 32 + kseg;
            uint32_t a[2][4], b[8][2];
            #pragma unroll
            for (int mt = 0; mt < 2; mt++)
                ldsm_x4(a[mt], sa + sw128((uint32_t)(m0 + mt * 16 + lrow) * 128 + kbyte));
            #pragma unroll
            for (int ntp = 0; ntp < 4; ntp++) {
                uint32_t r[4];
                ldsm_x4(r, sb + sw128((uint32_t)(n0 + ntp * 16 + lrow) * 128 + kbyte));
                b[2 * ntp][0] = r[0]; b[2 * ntp + 1][0] = r[1];
                b[2 * ntp][1] = r[2]; b[2 * ntp + 1][1] = r[3];
            }
            #pragma unroll
            for (int mt = 0; mt < 2; mt++)
                #pragma unroll
                for (int nt = 0; nt < 8; nt++)
                    mma_f16(acc[mt][nt], a[mt], b[nt]);
        }
    }

    // ---- epilogue: stage fp16 tile in smem (272B-padded rows), store coalesced
    __syncthreads();
    #pragma unroll
    for (int mt = 0; mt < 2; mt++) {
        const int rl = m0 + mt * 16 + l4;
        #pragma unroll
        for (int nt = 0; nt < 8; nt++) {
            const int cc = n0 + nt * 8 + lk * 2;
            *(__half2*)(tptr + rl * EPI_ROW_B + cc * 2) =
                __floats2half2_rn(acc[mt][nt][0], acc[mt][nt][1]);
            *(__half2*)(tptr + (rl + 8) * EPI_ROW_B + cc * 2) =
                __floats2half2_rn(acc[mt][nt][2], acc[mt][nt][3]);
        }
    }
    __syncthreads();
    #pragma unroll
    for (int i = 0; i < 8; i++) {
        const int c = tid + i * 256;     // 0..2047
        const int row = c >> 4, seg = c & 15;
        uint4 v = *(const uint4*)(tptr + row * EPI_ROW_B + seg * 16);
        *(uint4*)(Ch + (size_t)(row0 + row) * ldC + col0 + seg * 8) = v;
    }
}

// ---------------- weight prep: Wcath rows 768..1919 = WvT | W1aT | W1bT -------
__global__ void prep_w_kernel(__half* __restrict__ Wcath, const float* __restrict__ Wv,
                              const float* __restrict__ W1) {
    __shared__ float tile[32][33];
    const int r0 = blockIdx.x * 32;
    const int c0 = 768 + blockIdx.y * 32;
    const float* src; int stride, roff, coff;
    if      (c0 < 1536) { src = Wv; stride = DIM; roff = 0;   coff = c0 - 768; }
    else if (c0 < 1728) { src = W1; stride = HID; roff = 0;   coff = c0 - 1536; }
    else                { src = W1; stride = HID; roff = DIM; coff = c0 - 1728; }
    const int tx = threadIdx.x, ty = threadIdx.y;
    #pragma unroll
    for (int i = 0; i < 32; i += 8)
        tile[ty + i][tx] = src[(size_t)(roff + r0 + ty + i) * stride + coff + tx];
    __syncthreads();
    #pragma unroll
    for (int i = 0; i < 32; i += 8)
        Wcath[(size_t)(c0 + ty + i) * DIM + r0 + tx] = __float2half_rn(tile[tx][ty + i]);
}

// ---------------- fp16 conversion: x1,x2 -> Xh ; Wk,Wq -> Wkqh ---------------
__global__ void conv_h_kernel(__half* __restrict__ Xh, const float* __restrict__ x1,
                              const float* __restrict__ x2,
                              __half* __restrict__ Wkqh, const float* __restrict__ Wk,
                              const float* __restrict__ Wq) {
    const int n4x = NTOK * DIM / 4;
    const int n4w = DIM * DIM / 4;
    const int total = 2 * n4x + 2 * n4w;
    int i = blockIdx.x * blockDim.x + threadIdx.x;
    const int stride = gridDim.x * blockDim.x;
    for (; i < total; i += stride) {
        const float4* sp; __half2* dp; int j;
        if      (i < n4x)          { sp = (const float4*)x1; dp = (__half2*)Xh;                      j = i; }
        else if (i < 2 * n4x)      { sp = (const float4*)x2; dp = (__half2*)(Xh + (size_t)NTOK*DIM);  j = i - n4x; }
        else if (i < 2*n4x + n4w)  { sp = (const float4*)Wk; dp = (__half2*)Wkqh;                    j = i - 2*n4x; }
        else                       { sp = (const float4*)Wq; dp = (__half2*)(Wkqh + (size_t)DIM*DIM); j = i - 2*n4x - n4w; }
        float4 v = sp[j];
        dp[2*j]     = __floats2half2_rn(v.x, v.y);
        dp[2*j + 1] = __floats2half2_rn(v.z, v.w);
    }
}

// ---------------- fused epilogue (384 threads, vectorized, fp16 C) ------------
// C half offsets: Z@0, V@768, Pa@1536, Pb@1728. half2 units: Z[j], V[384+j].
__global__ void __launch_bounds__(384)
fuse2_kernel(const float* __restrict__ x1, const float* __restrict__ x2,
             const __half* __restrict__ C, const float* __restrict__ noise,
             const float* __restrict__ b1, const float* __restrict__ W2,
             const float* __restrict__ b2,
             float* __restrict__ y1, float* __restrict__ y2) {
    const int r = blockIdx.x;
    const __half2* C1 = (const __half2*)(C + (size_t)r * NC);
    const __half2* C2 = (const __half2*)(C + (size_t)(NTOK + r) * NC);
    const float2* X1 = (const float2*)(x1 + (size_t)r * DIM);
    const float2* X2 = (const float2*)(x2 + (size_t)r * DIM);
    const float2* NZ = (const float2*)noise;
    const int j = threadIdx.x;   // 0..383

    float t1 = 0.f, t2 = 0.f;
    if (j < HID) {
        const __half* C1h = (const __half*)C1;
        const __half* C2h = (const __half*)C2;
        float bb = b1[j], w = W2[j];
        float h1 = __half2float(C1h[1536 + j]) + __half2float(C2h[1728 + j]) + bb;
        float h2 = __half2float(C2h[1536 + j]) + __half2float(C1h[1728 + j]) + bb;
        h1 = 0.5f * h1 * (1.0f + erff(h1 * 0.7071067811865475f));
        h2 = 0.5f * h2 * (1.0f + erff(h2 * 0.7071067811865475f));
        t1 = h1 * w; t2 = h2 * w;
    }
    float2 z1 = __half22float2(C1[j]);
    float2 z2 = __half22float2(C2[j]);
    float2 xa = X1[j], xb = X2[j], nv = NZ[j];
    float s1 = z1.x * (xa.x + nv.x) + z1.y * (xa.y + nv.y);
    float c1 = z1.x * xb.x + z1.y * xb.y;
    float s2 = z2.x * (xb.x + nv.x) + z2.y * (xb.y + nv.y);
    float c2 = z2.x * xa.x + z2.y * xa.y;

    #pragma unroll
    for (int o = 16; o > 0; o >>= 1) {
        t1 += __shfl_down_sync(0xffffffffu, t1, o);
        t2 += __shfl_down_sync(0xffffffffu, t2, o);
        s1 += __shfl_down_sync(0xffffffffu, s1, o);
        c1 += __shfl_down_sync(0xffffffffu, c1, o);
        s2 += __shfl_down_sync(0xffffffffu, s2, o);
        c2 += __shfl_down_sync(0xffffffffu, c2, o);
    }
    __shared__ float sred[6][12];
    if ((j & 31) == 0) {
        int w = j >> 5;
        sred[0][w] = t1; sred[1][w] = t2;
        sred[2][w] = s1; sred[3][w] = c1;
        sred[4][w] = s2; sred[5][w] = c2;
    }
    __syncthreads();
    __shared__ float ws[4];
    if (j == 0) {
        float a[6];
        #pragma unroll
        for (int v = 0; v < 6; v++) {
            float acc = 0.f;
            #pragma unroll
            for (int w = 0; w < 12; w++) acc += sred[v][w];
            a[v] = acc;
        }
        const float bias = b2[0];
        const float rel1 = 1.0f / (1.0f + expf(-(a[0] + bias)));
        const float rel2 = 1.0f / (1.0f + expf(-(a[1] + bias)));
        const float scale = 0.03608439182435161f;  // 768^-0.5
        float d1s = a[2] * scale, d1c = a[3] * scale * rel1;
        float m = fmaxf(d1s, d1c);
        float e0 = expf(d1s - m), e1 = expf(d1c - m), inv = 1.0f / (e0 + e1);
        ws[0] = e0 * inv; ws[1] = e1 * inv;
        float d2s = a[4] * scale, d2c = a[5] * scale * rel2;
        m = fmaxf(d2s, d2c);
        e0 = expf(d2s - m); e1 = expf(d2c - m); inv = 1.0f / (e0 + e1);
        ws[2] = e0 * inv; ws[3] = e1 * inv;
    }
    __syncthreads();
    const float w10 = ws[0], w11 = ws[1], w20 = ws[2], w21 = ws[3];
    float2 v1 = __half22float2(C1[384 + j]);
    float2 v2 = __half22float2(C2[384 + j]);
    float2* Y1 = (float2*)(y1 + (size_t)r * DIM);
    float2* Y2 = (float2*)(y2 + (size_t)r * DIM);
    Y1[j] = make_float2(xa.x + w10 * v1.x + w11 * v2.x,
                        xa.y + w10 * v1.y + w11 * v2.y);
    Y2[j] = make_float2(xb.x + w20 * v2.x + w21 * v1.x,
                        xb.y + w20 * v2.y + w21 * v1.y);
}

// ---------------- host: tensormap construction -------------------------------
typedef CUresult (*EncodeTiledFn)(
    CUtensorMap*, CUtensorMapDataType, cuuint32_t, void*,
    const cuuint64_t*, const cuuint64_t*, const cuuint32_t*, const cuuint32_t*,
    CUtensorMapInterleave, CUtensorMapSwizzle, CUtensorMapL2promotion,
    CUtensorMapFloatOOBfill);

static void make_map_h(EncodeTiledFn enc, CUtensorMap* m, const void* base, uint64_t rows) {
    cuuint64_t dims[2]    = { (cuuint64_t)DIM, (cuuint64_t)rows };
    cuuint64_t strides[1] = { (cuuint64_t)DIM * sizeof(__half) };
    cuuint32_t box[2]     = { 64, 128 };
    cuuint32_t estr[2]    = { 1, 1 };
    enc(m, CU_TENSOR_MAP_DATA_TYPE_FLOAT16, 2, (void*)base, dims, strides, box, estr,
        CU_TENSOR_MAP_INTERLEAVE_NONE, CU_TENSOR_MAP_SWIZZLE_128B,
        CU_TENSOR_MAP_L2_PROMOTION_L2_128B, CU_TENSOR_MAP_FLOAT_OOB_FILL_NONE);
}

// ---------------- launch --------------------------------------------------------
extern "C" void kernel_launch(void* const* d_in, const int* in_sizes, int n_in,
                              void* d_out, int out_size) {
    const float* x1    = (const float*)d_in[0];
    const float* x2    = (const float*)d_in[1];
    const float* Wq    = (const float*)d_in[2];
    const float* Wk    = (const float*)d_in[3];
    const float* Wv    = (const float*)d_in[4];
    const float* noise = (const float*)d_in[5];
    const float* W1    = (const float*)d_in[6];
    const float* b1    = (const float*)d_in[7];
    const float* W2    = (const float*)d_in[8];
    const float* b2    = (const float*)d_in[9];

    __half *Wcath, *Wkqh, *Xh, *Ch;
    cudaGetSymbolAddress((void**)&Wcath, g_Wcath);
    cudaGetSymbolAddress((void**)&Wkqh,  g_Wkqh);
    cudaGetSymbolAddress((void**)&Xh,    g_Xh);
    cudaGetSymbolAddress((void**)&Ch,    g_Ch);

    static bool init_done = false;
    static CUtensorMap mapXh, mapWh, mapWkh, mapWqh;
    if (!init_done) {
        cudaFuncSetAttribute(gemm_f16_kernel,
                             cudaFuncAttributeMaxDynamicSharedMemorySize, SMEM_TOTAL);
        EncodeTiledFn enc = nullptr;
        cudaDriverEntryPointQueryResult qr;
        cudaGetDriverEntryPoint("cuTensorMapEncodeTiled", (void**)&enc,
                                cudaEnableDefault, &qr);
        make_map_h(enc, &mapXh,  Xh,    NROWS);
        make_map_h(enc, &mapWh,  Wcath, NC);
        make_map_h(enc, &mapWkh, Wkqh,  DIM);
        make_map_h(enc, &mapWqh, Wkqh + (size_t)DIM * DIM, DIM);
        init_done = true;
    }

    cudaStream_t s = 0;

    // 0: Wcath rows 768..1919 (WvT | W1aT | W1bT), fp16
    prep_w_kernel<<<dim3(24, 36), dim3(32, 8), 0, s>>>(Wcath, Wv, W1);
    // 1: fp16 conversion of x1,x2,Wk,Wq
    conv_h_kernel<<<1184, 256, 0, s>>>(Xh, x1, x2, Wkqh, Wk, Wq);
    // 2: Gh = Wkh @ Wqh^T into Wcath rows 0..767 (fp16 output)
    gemm_f16_kernel<<<dim3(6, 6), 256, SMEM_TOTAL, s>>>(mapWkh, mapWqh, Wcath, DIM);
    // 3: main GEMM Ch = Xh @ Wcath^T (profiled slot)
    dim3 grid(NC / BN, NROWS / BM);
    gemm_f16_kernel<<<grid, 256, SMEM_TOTAL, s>>>(mapXh, mapWh, Ch, NC);
    // 4: fused epilogue
    float* y1 = (float*)d_out;
    float* y2 = y1 + (size_t)NTOK * DIM;
    fuse2_kernel<<<NTOK, 384, 0, s>>>(x1, x2, Ch, noise, b1, W2, b2, y1, y2);
}

// round 15
// speedup vs baseline: 1.1263x; 1.1263x over previous
#include <cuda_runtime.h>
#include <cuda.h>
#include <cuda_fp16.h>
#include <math.h>
#include <stdint.h>

// ---------------- problem constants ----------------
#define NTOK   (32*1024)        // B*N rows per input
#define NROWS  (2*NTOK)
#define DIM    768
#define HID    192
#define NC     1920             // fused output cols: Z|V|Pa|Pb
#define NKT    12               // 12 k-tiles of 64 halves

// GEMM tiling: 128x128 CTA tile, 8 warps (4m x 2n), warp tile 32x64, k-tile 64
#define BM 128
#define BN 128
#define TILE_BYTES 16384                  // 128 rows x 128B (64 halves)
#define STAGE_BYTES (2*TILE_BYTES)
#define NSTAGE 3
#define SMEM_TOTAL (1024 + NSTAGE*STAGE_BYTES + 64)
#define EPI_ROW_B 272                     // epilogue staging row pitch (bytes)

// ---------------- scratch ----------------
__device__ __align__(1024) __half g_Wcath[(size_t)NC*DIM];     // fp16 [1920,768]: Gh|WvT|W1aT|W1bT
__device__ __align__(1024) __half g_Wkqh[(size_t)2*DIM*DIM];   // fp16 [Wk;Wq]
__device__ __align__(1024) __half g_Xh[(size_t)NROWS*DIM];     // fp16 [x1;x2]
__device__ __align__(1024) __half g_Ch[(size_t)NROWS*NC];      // fp16 [C1;C2]

// ---------------- device helpers ----------------
__device__ __forceinline__ uint32_t smem_u32(const void* p) {
    uint32_t a;
    asm("{ .reg .u64 t; cvta.to.shared.u64 t, %1; cvt.u32.u64 %0, t; }" : "=r"(a) : "l"(p));
    return a;
}
__device__ __forceinline__ uint32_t sw128(uint32_t off) { return off ^ ((off >> 3) & 0x70); }

#define MBAR_INIT(a, c) asm volatile("mbarrier.init.shared.b64 [%0], %1;" :: "r"(a), "r"(c) : "memory")
#define MBAR_EXPECT(a, bytes) \
    asm volatile("mbarrier.arrive.expect_tx.shared.b64 _, [%0], %1;" :: "r"(a), "r"(bytes) : "memory")
#define MBAR_WAIT(a, ph) do { \
    uint32_t _m = (a), _p = (ph), _d; \
    asm volatile("{ .reg .pred p; mbarrier.try_wait.parity.acquire.cta.shared::cta.b64 p, [%1], %2; selp.b32 %0,1,0,p; }" \
        : "=r"(_d) : "r"(_m), "r"(_p) : "memory"); \
    if (!_d) { \
        asm volatile("{ .reg .pred P1; WL_%=: mbarrier.try_wait.parity.acquire.cta.shared::cta.b64 P1, [%0], %1, 0x989680;" \
                     " @P1 bra.uni WD_%=; bra.uni WL_%=; WD_%=: }" :: "r"(_m), "r"(_p) : "memory"); \
    } } while(0)

__device__ __forceinline__ void tma_2d(uint32_t dst, const void* tmap, int x, int y, uint32_t mbar) {
    asm volatile("cp.async.bulk.tensor.2d.shared::cta.global.tile.mbarrier::complete_tx::bytes "
                 "[%0], [%1, {%2, %3}], [%4];"
                 :: "r"(dst), "l"(tmap), "r"(x), "r"(y), "r"(mbar) : "memory");
}
__device__ __forceinline__ void ldsm_x4(uint32_t* r, uint32_t addr) {
    asm volatile("ldmatrix.sync.aligned.m8n8.x4.shared.b16 {%0,%1,%2,%3}, [%4];"
                 : "=r"(r[0]), "=r"(r[1]), "=r"(r[2]), "=r"(r[3]) : "r"(addr));
}
__device__ __forceinline__ void mma_f16(float* c, const uint32_t* a, const uint32_t* b) {
    asm volatile("mma.sync.aligned.m16n8k16.row.col.f32.f16.f16.f32 "
                 "{%0,%1,%2,%3}, {%4,%5,%6,%7}, {%8,%9}, {%0,%1,%2,%3};"
                 : "+f"(c[0]), "+f"(c[1]), "+f"(c[2]), "+f"(c[3])
                 : "r"(a[0]), "r"(a[1]), "r"(a[2]), "r"(a[3]), "r"(b[0]), "r"(b[1]));
}

// ---------------- fp16 TMA GEMM: Ch[·,ldC] = A[·,768] @ Bt[·,768]^T -----------
__global__ void __launch_bounds__(256, 2)
gemm_f16_kernel(const __grid_constant__ CUtensorMap tmap_a,
                const __grid_constant__ CUtensorMap tmap_b,
                __half* __restrict__ Ch, int ldC) {
    extern __shared__ char smem[];
    const uint32_t sraw = smem_u32(smem);
    const uint32_t tbase = (sraw + 1023u) & ~1023u;
    char* tptr = smem + (tbase - sraw);
    const uint32_t mbar0 = tbase + NSTAGE * STAGE_BYTES;

    const int tid = threadIdx.x;
    const int lane = tid & 31, wid = tid >> 5;
    const int l4 = lane >> 2, lk = lane & 3;
    const int row0 = blockIdx.y * BM;
    const int col0 = blockIdx.x * BN;
    const int m0 = (wid & 3) * 32;
    const int n0 = (wid >> 2) * 64;

    const int lrow = (lane & 7) + 8 * ((lane >> 3) & 1);
    const uint32_t kseg = ((uint32_t)(lane >> 4)) << 4;

    if (tid == 0) {
        #pragma unroll
        for (int s = 0; s < NSTAGE; s++) MBAR_INIT(mbar0 + 8 * s, 1);
    }
    __syncthreads();

    if (tid == 0) {
        #pragma unroll
        for (int t = 0; t < 2; t++) {
            const uint32_t mb = mbar0 + 8 * t;
            const uint32_t sa = tbase + t * STAGE_BYTES;
            MBAR_EXPECT(mb, STAGE_BYTES);
            tma_2d(sa,              &tmap_a, t * 64, row0, mb);
            tma_2d(sa + TILE_BYTES, &tmap_b, t * 64, col0, mb);
        }
    }

    float acc[2][8][4];
    #pragma unroll
    for (int mt = 0; mt < 2; mt++)
        #pragma unroll
        for (int nt = 0; nt < 8; nt++)
            #pragma unroll
            for (int j = 0; j < 4; j++) acc[mt][nt][j] = 0.f;

    for (int kt = 0; kt < NKT; kt++) {
        const int s = kt % 3;
        __syncthreads();
        if (tid == 0 && kt + 2 < NKT) {
            const int t = kt + 2, s2 = t % 3;
            const uint32_t mb = mbar0 + 8 * s2;
            const uint32_t sa = tbase + s2 * STAGE_BYTES;
            MBAR_EXPECT(mb, STAGE_BYTES);
            tma_2d(sa,              &tmap_a, t * 64, row0, mb);
            tma_2d(sa + TILE_BYTES, &tmap_b, t * 64, col0, mb);
        }
        MBAR_WAIT(mbar0 + 8 * s, (kt / 3) & 1);

        const uint32_t sa = tbase + s * STAGE_BYTES;
        const uint32_t sb = sa + TILE_BYTES;

        #pragma unroll
        for (int ks = 0; ks < 4; ks++) {
            const uint32_t kbyte = ks * 32 + kseg;
            uint32_t a[2][4], b[8][2];
            #pragma unroll
            for (int mt = 0; mt < 2; mt++)
                ldsm_x4(a[mt], sa + sw128((uint32_t)(m0 + mt * 16 + lrow) * 128 + kbyte));
            #pragma unroll
            for (int ntp = 0; ntp < 4; ntp++) {
                uint32_t r[4];
                ldsm_x4(r, sb + sw128((uint32_t)(n0 + ntp * 16 + lrow) * 128 + kbyte));
                b[2 * ntp][0] = r[0]; b[2 * ntp + 1][0] = r[1];
                b[2 * ntp][1] = r[2]; b[2 * ntp + 1][1] = r[3];
            }
            #pragma unroll
            for (int mt = 0; mt < 2; mt++)
                #pragma unroll
                for (int nt = 0; nt < 8; nt++)
                    mma_f16(acc[mt][nt], a[mt], b[nt]);
        }
    }

    // epilogue: stage fp16 tile in smem, store coalesced uint4 rows
    __syncthreads();
    #pragma unroll
    for (int mt = 0; mt < 2; mt++) {
        const int rl = m0 + mt * 16 + l4;
        #pragma unroll
        for (int nt = 0; nt < 8; nt++) {
            const int cc = n0 + nt * 8 + lk * 2;
            *(__half2*)(tptr + rl * EPI_ROW_B + cc * 2) =
                __floats2half2_rn(acc[mt][nt][0], acc[mt][nt][1]);
            *(__half2*)(tptr + (rl + 8) * EPI_ROW_B + cc * 2) =
                __floats2half2_rn(acc[mt][nt][2], acc[mt][nt][3]);
        }
    }
    __syncthreads();
    #pragma unroll
    for (int i = 0; i < 8; i++) {
        const int c = tid + i * 256;
        const int row = c >> 4, seg = c & 15;
        uint4 v = *(const uint4*)(tptr + row * EPI_ROW_B + seg * 16);
        *(uint4*)(Ch + (size_t)(row0 + row) * ldC + col0 + seg * 8) = v;
    }
}

// ---------------- weight prep: Wcath rows 768..1919 = WvT | W1aT | W1bT -------
__global__ void prep_w_kernel(__half* __restrict__ Wcath, const float* __restrict__ Wv,
                              const float* __restrict__ W1) {
    __shared__ float tile[32][33];
    const int r0 = blockIdx.x * 32;
    const int c0 = 768 + blockIdx.y * 32;
    const float* src; int stride, roff, coff;
    if      (c0 < 1536) { src = Wv; stride = DIM; roff = 0;   coff = c0 - 768; }
    else if (c0 < 1728) { src = W1; stride = HID; roff = 0;   coff = c0 - 1536; }
    else                { src = W1; stride = HID; roff = DIM; coff = c0 - 1728; }
    const int tx = threadIdx.x, ty = threadIdx.y;
    #pragma unroll
    for (int i = 0; i < 32; i += 8)
        tile[ty + i][tx] = src[(size_t)(roff + r0 + ty + i) * stride + coff + tx];
    __syncthreads();
    #pragma unroll
    for (int i = 0; i < 32; i += 8)
        Wcath[(size_t)(c0 + ty + i) * DIM + r0 + tx] = __float2half_rn(tile[tx][ty + i]);
}

// ---------------- fp16 conversion: x1,x2 -> Xh ; Wk,Wq -> Wkqh ---------------
__global__ void conv_h_kernel(__half* __restrict__ Xh, const float* __restrict__ x1,
                              const float* __restrict__ x2,
                              __half* __restrict__ Wkqh, const float* __restrict__ Wk,
                              const float* __restrict__ Wq) {
    const int n4x = NTOK * DIM / 4;
    const int n4w = DIM * DIM / 4;
    const int total = 2 * n4x + 2 * n4w;
    int i = blockIdx.x * blockDim.x + threadIdx.x;
    const int stride = gridDim.x * blockDim.x;
    for (; i < total; i += stride) {
        const float4* sp; __half2* dp; int j;
        if      (i < n4x)          { sp = (const float4*)x1; dp = (__half2*)Xh;                      j = i; }
        else if (i < 2 * n4x)      { sp = (const float4*)x2; dp = (__half2*)(Xh + (size_t)NTOK*DIM);  j = i - n4x; }
        else if (i < 2*n4x + n4w)  { sp = (const float4*)Wk; dp = (__half2*)Wkqh;                    j = i - 2*n4x; }
        else                       { sp = (const float4*)Wq; dp = (__half2*)(Wkqh + (size_t)DIM*DIM); j = i - 2*n4x - n4w; }
        float4 v = sp[j];
        dp[2*j]     = __floats2half2_rn(v.x, v.y);
        dp[2*j + 1] = __floats2half2_rn(v.z, v.w);
    }
}

// ---------------- fused epilogue: warp-per-row, shuffle-only reduction --------
// uint2 view of C row: Z at [0,192), V at [192,384). half2 view: Pa@768, Pb@864.
__global__ void __launch_bounds__(256)
fuse2_kernel(const float* __restrict__ x1, const float* __restrict__ x2,
             const __half* __restrict__ C, const float* __restrict__ noise,
             const float* __restrict__ b1, const float* __restrict__ W2,
             const float* __restrict__ b2,
             float* __restrict__ y1, float* __restrict__ y2) {
    const int warp = threadIdx.x >> 5;
    const int lane = threadIdx.x & 31;
    const int r = blockIdx.x * 8 + warp;

    const uint2*   C1v = (const uint2*)(C + (size_t)r * NC);
    const uint2*   C2v = (const uint2*)(C + (size_t)(NTOK + r) * NC);
    const __half2* C1h = (const __half2*)(C + (size_t)r * NC);
    const __half2* C2h = (const __half2*)(C + (size_t)(NTOK + r) * NC);
    const float4*  X1v = (const float4*)(x1 + (size_t)r * DIM);
    const float4*  X2v = (const float4*)(x2 + (size_t)r * DIM);
    const float4*  NZv = (const float4*)noise;
    const float2*  B1v = (const float2*)b1;
    const float2*  W2v = (const float2*)W2;

    float s1 = 0.f, c1 = 0.f, s2 = 0.f, c2 = 0.f, t1 = 0.f, t2 = 0.f;

    // dot partials: 6 coalesced rounds of 4 cols per lane
    #pragma unroll
    for (int k = 0; k < 6; k++) {
        const int m = k * 32 + lane;
        uint2 za = C1v[m], zb = C2v[m];
        float4 a = X1v[m], b = X2v[m], n = NZv[m];
        float2 z1l = __half22float2(*(__half2*)&za.x);
        float2 z1h = __half22float2(*(__half2*)&za.y);
        float2 z2l = __half22float2(*(__half2*)&zb.x);
        float2 z2h = __half22float2(*(__half2*)&zb.y);
        s1 += z1l.x*(a.x+n.x) + z1l.y*(a.y+n.y) + z1h.x*(a.z+n.z) + z1h.y*(a.w+n.w);
        c1 += z1l.x*b.x + z1l.y*b.y + z1h.x*b.z + z1h.y*b.w;
        s2 += z2l.x*(b.x+n.x) + z2l.y*(b.y+n.y) + z2h.x*(b.z+n.z) + z2h.y*(b.w+n.w);
        c2 += z2l.x*a.x + z2l.y*a.y + z2h.x*a.z + z2h.y*a.w;
    }
    // gate partials: 3 coalesced rounds of 2 cols per lane (96 half2 total)
    #pragma unroll
    for (int k = 0; k < 3; k++) {
        const int idx = k * 32 + lane;
        float2 pa1 = __half22float2(C1h[768 + idx]);
        float2 pb1 = __half22float2(C1h[864 + idx]);
        float2 pa2 = __half22float2(C2h[768 + idx]);
        float2 pb2 = __half22float2(C2h[864 + idx]);
        float2 bb = B1v[idx], w = W2v[idx];
        float h1x = pa1.x + pb2.x + bb.x, h1y = pa1.y + pb2.y + bb.y;
        float h2x = pa2.x + pb1.x + bb.x, h2y = pa2.y + pb1.y + bb.y;
        h1x = 0.5f * h1x * (1.0f + erff(h1x * 0.7071067811865475f));
        h1y = 0.5f * h1y * (1.0f + erff(h1y * 0.7071067811865475f));
        h2x = 0.5f * h2x * (1.0f + erff(h2x * 0.7071067811865475f));
        h2y = 0.5f * h2y * (1.0f + erff(h2y * 0.7071067811865475f));
        t1 += h1x * w.x + h1y * w.y;
        t2 += h2x * w.x + h2y * w.y;
    }

    // warp reduction (shuffles only)
    #pragma unroll
    for (int o = 16; o > 0; o >>= 1) {
        s1 += __shfl_down_sync(0xffffffffu, s1, o);
        c1 += __shfl_down_sync(0xffffffffu, c1, o);
        s2 += __shfl_down_sync(0xffffffffu, s2, o);
        c2 += __shfl_down_sync(0xffffffffu, c2, o);
        t1 += __shfl_down_sync(0xffffffffu, t1, o);
        t2 += __shfl_down_sync(0xffffffffu, t2, o);
    }
    float w10, w11, w20, w21;
    if (lane == 0) {
        const float bias = b2[0];
        const float rel1 = 1.0f / (1.0f + expf(-(t1 + bias)));
        const float rel2 = 1.0f / (1.0f + expf(-(t2 + bias)));
        const float scale = 0.03608439182435161f;  // 768^-0.5
        float d1s = s1 * scale, d1c = c1 * scale * rel1;
        float m = fmaxf(d1s, d1c);
        float e0 = expf(d1s - m), e1 = expf(d1c - m), inv = 1.0f / (e0 + e1);
        w10 = e0 * inv; w11 = e1 * inv;
        float d2s = s2 * scale, d2c = c2 * scale * rel2;
        m = fmaxf(d2s, d2c);
        e0 = expf(d2s - m); e1 = expf(d2c - m); inv = 1.0f / (e0 + e1);
        w20 = e0 * inv; w21 = e1 * inv;
    }
    w10 = __shfl_sync(0xffffffffu, w10, 0);
    w11 = __shfl_sync(0xffffffffu, w11, 0);
    w20 = __shfl_sync(0xffffffffu, w20, 0);
    w21 = __shfl_sync(0xffffffffu, w21, 0);

    // output: y = x + w*V (6 coalesced rounds)
    float4* Y1v = (float4*)(y1 + (size_t)r * DIM);
    float4* Y2v = (float4*)(y2 + (size_t)r * DIM);
    #pragma unroll
    for (int k = 0; k < 6; k++) {
        const int m = k * 32 + lane;
        uint2 va = C1v[192 + m], vb = C2v[192 + m];
        float4 a = X1v[m], b = X2v[m];
        float2 v1l = __half22float2(*(__half2*)&va.x);
        float2 v1h = __half22float2(*(__half2*)&va.y);
        float2 v2l = __half22float2(*(__half2*)&vb.x);
        float2 v2h = __half22float2(*(__half2*)&vb.y);
        float4 o1 = make_float4(a.x + w10*v1l.x + w11*v2l.x,
                                a.y + w10*v1l.y + w11*v2l.y,
                                a.z + w10*v1h.x + w11*v2h.x,
                                a.w + w10*v1h.y + w11*v2h.y);
        float4 o2 = make_float4(b.x + w20*v2l.x + w21*v1l.x,
                                b.y + w20*v2l.y + w21*v1l.y,
                                b.z + w20*v2h.x + w21*v1h.x,
                                b.w + w20*v2h.y + w21*v1h.y);
        Y1v[m] = o1;
        Y2v[m] = o2;
    }
}

// ---------------- host: tensormap construction -------------------------------
typedef CUresult (*EncodeTiledFn)(
    CUtensorMap*, CUtensorMapDataType, cuuint32_t, void*,
    const cuuint64_t*, const cuuint64_t*, const cuuint32_t*, const cuuint32_t*,
    CUtensorMapInterleave, CUtensorMapSwizzle, CUtensorMapL2promotion,
    CUtensorMapFloatOOBfill);

static void make_map_h(EncodeTiledFn enc, CUtensorMap* m, const void* base, uint64_t rows) {
    cuuint64_t dims[2]    = { (cuuint64_t)DIM, (cuuint64_t)rows };
    cuuint64_t strides[1] = { (cuuint64_t)DIM * sizeof(__half) };
    cuuint32_t box[2]     = { 64, 128 };
    cuuint32_t estr[2]    = { 1, 1 };
    enc(m, CU_TENSOR_MAP_DATA_TYPE_FLOAT16, 2, (void*)base, dims, strides, box, estr,
        CU_TENSOR_MAP_INTERLEAVE_NONE, CU_TENSOR_MAP_SWIZZLE_128B,
        CU_TENSOR_MAP_L2_PROMOTION_L2_128B, CU_TENSOR_MAP_FLOAT_OOB_FILL_NONE);
}

// ---------------- launch --------------------------------------------------------
extern "C" void kernel_launch(void* const* d_in, const int* in_sizes, int n_in,
                              void* d_out, int out_size) {
    const float* x1    = (const float*)d_in[0];
    const float* x2    = (const float*)d_in[1];
    const float* Wq    = (const float*)d_in[2];
    const float* Wk    = (const float*)d_in[3];
    const float* Wv    = (const float*)d_in[4];
    const float* noise = (const float*)d_in[5];
    const float* W1    = (const float*)d_in[6];
    const float* b1    = (const float*)d_in[7];
    const float* W2    = (const float*)d_in[8];
    const float* b2    = (const float*)d_in[9];

    __half *Wcath, *Wkqh, *Xh, *Ch;
    cudaGetSymbolAddress((void**)&Wcath, g_Wcath);
    cudaGetSymbolAddress((void**)&Wkqh,  g_Wkqh);
    cudaGetSymbolAddress((void**)&Xh,    g_Xh);
    cudaGetSymbolAddress((void**)&Ch,    g_Ch);

    static bool init_done = false;
    static CUtensorMap mapXh, mapWh, mapWkh, mapWqh;
    if (!init_done) {
        cudaFuncSetAttribute(gemm_f16_kernel,
                             cudaFuncAttributeMaxDynamicSharedMemorySize, SMEM_TOTAL);
        EncodeTiledFn enc = nullptr;
        cudaDriverEntryPointQueryResult qr;
        cudaGetDriverEntryPoint("cuTensorMapEncodeTiled", (void**)&enc,
                                cudaEnableDefault, &qr);
        make_map_h(enc, &mapXh,  Xh,    NROWS);
        make_map_h(enc, &mapWh,  Wcath, NC);
        make_map_h(enc, &mapWkh, Wkqh,  DIM);
        make_map_h(enc, &mapWqh, Wkqh + (size_t)DIM * DIM, DIM);
        init_done = true;
    }

    cudaStream_t s = 0;

    // 0: Wcath rows 768..1919 (WvT | W1aT | W1bT), fp16
    prep_w_kernel<<<dim3(24, 36), dim3(32, 8), 0, s>>>(Wcath, Wv, W1);
    // 1: fp16 conversion of x1,x2,Wk,Wq
    conv_h_kernel<<<1184, 256, 0, s>>>(Xh, x1, x2, Wkqh, Wk, Wq);
    // 2: Gh = Wkh @ Wqh^T into Wcath rows 0..767 (fp16 output)
    gemm_f16_kernel<<<dim3(6, 6), 256, SMEM_TOTAL, s>>>(mapWkh, mapWqh, Wcath, DIM);
    // 3: main GEMM Ch = Xh @ Wcath^T (profiled slot)
    dim3 grid(NC / BN, NROWS / BM);
    gemm_f16_kernel<<<grid, 256, SMEM_TOTAL, s>>>(mapXh, mapWh, Ch, NC);
    // 4: fused epilogue, warp-per-row
    float* y1 = (float*)d_out;
    float* y2 = y1 + (size_t)NTOK * DIM;
    fuse2_kernel<<<NTOK / 8, 256, 0, s>>>(x1, x2, Ch, noise, b1, W2, b2, y1, y2);
}